// round 1
// baseline (speedup 1.0000x reference)
#include <cuda_runtime.h>
#include <cstdint>

// S4D kernel generation: K[h,l] = 2*Re( sum_n Cc[h,n] * exp(dtA[h,n]*l) )
// H=1024, N2=32, L=4096.
//
// Strategy:
//  - Each mode's real part Re(cc * r^l) satisfies the stable 2nd-order real
//    recurrence  u_{l+S} = 2Re(r^S) u_l - |r^S|^2 u_{l-S}  with S = 64.
//  - Pass 1 precomputes per (h,n): the recurrence constants and the initial
//    state table Re(cc * r^l) for l in [-64, 64) (sequential complex muls).
//  - Main kernel: block = one h, 64 threads; thread tid emits l = tid + 64k.
//    16 mode-pairs packed in f32x2 registers; 2nd-order advance = 1 mul.f32x2
//    + 1 fma.f32x2 per pair, tree-sum with add.f32x2. Coalesced stores.

#define MAXH 1024
#define N2C  32        // complex modes per h (compile-time; problem-fixed)
#define NP   (N2C/2)   // packed pairs = 16
#define BT   64        // block threads = l-stride S

typedef unsigned long long ull;

__device__ float  g_U[MAXH * 2 * BT * N2C];   // rows jj=0..127 -> l = jj-64
__device__ float2 g_T[MAXH * N2C];            // (2*Re(R), -|R|^2), R = r^64

__device__ __forceinline__ ull pk(float lo, float hi) {
    ull r; asm("mov.b64 %0,{%1,%2};" : "=l"(r) : "f"(lo), "f"(hi)); return r;
}
__device__ __forceinline__ void upk(ull v, float& lo, float& hi) {
    asm("mov.b64 {%0,%1},%2;" : "=f"(lo), "=f"(hi) : "l"(v));
}
__device__ __forceinline__ ull mul2(ull a, ull b) {
    ull d; asm("mul.rn.f32x2 %0,%1,%2;" : "=l"(d) : "l"(a), "l"(b)); return d;
}
__device__ __forceinline__ ull add2(ull a, ull b) {
    ull d; asm("add.rn.f32x2 %0,%1,%2;" : "=l"(d) : "l"(a), "l"(b)); return d;
}
__device__ __forceinline__ ull fma2(ull a, ull b, ull c) {
    ull d; asm("fma.rn.f32x2 %0,%1,%2,%3;" : "=l"(d) : "l"(a), "l"(b), "l"(c)); return d;
}

// ---------------- Pass 1: constants + initial-state table -------------------
__global__ void s4d_pass1(const float* __restrict__ C,
                          const float* __restrict__ log_dt,
                          const float* __restrict__ lAr,
                          const float* __restrict__ Ai,
                          int HN) {
    int idx = blockIdx.x * blockDim.x + threadIdx.x;
    if (idx >= HN) return;
    int h = idx / N2C;
    int n = idx % N2C;

    float dt = expf(log_dt[h]);
    float ar = -expf(lAr[idx]);
    float ai = Ai[idx];
    float x = ar * dt;            // Re(dtA)  (negative)
    float y = ai * dt;            // Im(dtA)

    // r = exp(dtA)
    float ex = expf(x), sy, cy;
    sincosf(y, &sy, &cy);
    float rre = ex * cy, rim = ex * sy;

    // cc = 2*C*(r-1)/A  (A = ar + i*ai), fold factor 2 here
    float den = ar * ar + ai * ai;
    float c2  = 2.0f * C[idx] / den;
    float wre = rre - 1.0f, wim = rim;
    float ccre = c2 * (wre * ar + wim * ai);
    float ccim = c2 * (wim * ar - wre * ai);

    // R = r^64: constants for the stride-64 real recurrence
    float eR = expf(64.0f * x);
    float s64, c64;
    sincosf(64.0f * y, &s64, &c64);
    g_T[idx] = make_float2(2.0f * eR * c64, -expf(128.0f * x));

    // start state s = cc * r^(-64) = cc * exp(-64x) * (cos64y - i sin64y)
    float e0 = expf(-64.0f * x);
    float sre = e0 * (ccre * c64 + ccim * s64);
    float sim = e0 * (ccim * c64 - ccre * s64);

    // write Re(cc*r^l) for l = -64..63  (rows jj = l+64), column n
    float* up = g_U + h * (2 * BT * N2C) + n;
    #pragma unroll 4
    for (int jj = 0; jj < 2 * BT; ++jj) {
        up[jj * N2C] = sre;
        float t = fmaf(sre, rre, -sim * rim);
        sim = fmaf(sre, rim, sim * rre);
        sre = t;
    }
}

// ---------------- Main: packed 2nd-order recurrence -------------------------
__global__ void __launch_bounds__(BT)
s4d_main(float* __restrict__ out, int L) {
    const int h   = blockIdx.x;
    const int tid = threadIdx.x;

    __shared__ ull s_tA[NP], s_mN[NP];
    if (tid < NP) {
        float2 a = g_T[h * N2C + 2 * tid];
        float2 b = g_T[h * N2C + 2 * tid + 1];
        s_tA[tid] = pk(a.x, b.x);
        s_mN[tid] = pk(a.y, b.y);
    }
    __syncthreads();

    // states: um1 holds l = tid-64 row, u0 holds l = tid row (8B = one pair)
    const ull* u_m = (const ull*)(g_U + (h * 2 * BT + tid) * N2C);
    const ull* u_0 = (const ull*)(g_U + (h * 2 * BT + tid + BT) * N2C);
    ull um1[NP], u0[NP];
    #pragma unroll
    for (int i = 0; i < NP; ++i) { um1[i] = u_m[i]; u0[i] = u_0[i]; }

    float* op = out + h * L + tid;
    const int KS = L / BT;   // 64

    for (int k = 0; k < KS; k += 2) {
        // ---- emit output at l = tid + 64k  (from u0), tree reduce ----
        {
            ull a8[8];
            #pragma unroll
            for (int i = 0; i < 8; ++i) a8[i] = add2(u0[2 * i], u0[2 * i + 1]);
            ull a4_0 = add2(a8[0], a8[1]), a4_1 = add2(a8[2], a8[3]);
            ull a4_2 = add2(a8[4], a8[5]), a4_3 = add2(a8[6], a8[7]);
            ull acc  = add2(add2(a4_0, a4_1), add2(a4_2, a4_3));
            float lo, hi; upk(acc, lo, hi);
            op[k * BT] = lo + hi;
        }
        // ---- advance: um1 <- u_{k+1} ----
        #pragma unroll
        for (int i = 0; i < NP; ++i)
            um1[i] = fma2(u0[i], s_tA[i], mul2(um1[i], s_mN[i]));

        // ---- emit output at l = tid + 64(k+1) (from um1) ----
        {
            ull a8[8];
            #pragma unroll
            for (int i = 0; i < 8; ++i) a8[i] = add2(um1[2 * i], um1[2 * i + 1]);
            ull a4_0 = add2(a8[0], a8[1]), a4_1 = add2(a8[2], a8[3]);
            ull a4_2 = add2(a8[4], a8[5]), a4_3 = add2(a8[6], a8[7]);
            ull acc  = add2(add2(a4_0, a4_1), add2(a4_2, a4_3));
            float lo, hi; upk(acc, lo, hi);
            op[(k + 1) * BT] = lo + hi;
        }
        // ---- advance: u0 <- u_{k+2} ----
        #pragma unroll
        for (int i = 0; i < NP; ++i)
            u0[i] = fma2(um1[i], s_tA[i], mul2(u0[i], s_mN[i]));
    }
}

// ---------------- launch ----------------------------------------------------
extern "C" void kernel_launch(void* const* d_in, const int* in_sizes, int n_in,
                              void* d_out, int out_size) {
    const float* C      = (const float*)d_in[0];
    const float* log_dt = (const float*)d_in[1];
    const float* lAr    = (const float*)d_in[2];
    const float* Ai     = (const float*)d_in[3];
    // d_in[4] is L on device; recover shapes from host-visible sizes instead.
    const int H  = in_sizes[1];          // 1024
    const int HN = in_sizes[0];          // H * N2 = 32768
    const int L  = out_size / H;         // 4096

    s4d_pass1<<<(HN + 127) / 128, 128>>>(C, log_dt, lAr, Ai, HN);
    s4d_main<<<H, BT>>>((float*)d_out, L);
}